// round 2
// baseline (speedup 1.0000x reference)
#include <cuda_runtime.h>
#include <math.h>

// Problem constants
#define NB   8
#define T1   512
#define T2   128
#define EE   64      // E
#define G3   192     // 3*E
#define DLN  256
#define CTXD 128     // 2*E

// Scratch (device globals; no allocation allowed)
__device__ float g_Xg[2 * NB * T2 * G3];     // pre-activations x@K + b0, per dir
__device__ float g_ctx[NB * T2 * CTXD];      // [b][s][fwd(64)|bwd(64)]
__device__ float g_P0[NB * T2 * EE];
__device__ float g_P1[NB * T2 * EE];
__device__ float g_Q00[NB * T2 * EE];
__device__ float g_Qm [NB * T2 * EE];
__device__ float g_Q11[NB * T2 * EE];
__device__ float g_cs[NB * T2];              // ctx . w_c
__device__ float g_a [NB * T1];              // lstm . w_l
__device__ float g_bias2[EE];

// ---------------------------------------------------------------------------
// Kernel A: embedding lookup + input-gate precompute  Xg = emb@K + b[0]
// grid: 1024 (b*128+t), block: 384 (dir*192+u)
// ---------------------------------------------------------------------------
__global__ void k_embed_xg(const int* __restrict__ char_seq,
                           const float* __restrict__ emb_table,
                           const float* __restrict__ Kf, const float* __restrict__ bf,
                           const float* __restrict__ Kb, const float* __restrict__ bb) {
    int bt = blockIdx.x;
    __shared__ float e_sm[EE];
    int tid = threadIdx.x;
    if (tid < EE) {
        int c = char_seq[bt];
        e_sm[tid] = emb_table[c * EE + tid];
    }
    __syncthreads();
    int dir = tid / G3;
    int u   = tid - dir * G3;
    const float* K    = dir ? Kb : Kf;
    const float* bias = dir ? bb : bf;
    float acc = bias[u];
    const float4* e4 = (const float4*)e_sm;
#pragma unroll
    for (int e4i = 0; e4i < EE / 4; e4i++) {
        float4 hv = e4[e4i];
        int e = e4i * 4;
        acc = fmaf(hv.x, K[(e + 0) * G3 + u], acc);
        acc = fmaf(hv.y, K[(e + 1) * G3 + u], acc);
        acc = fmaf(hv.z, K[(e + 2) * G3 + u], acc);
        acc = fmaf(hv.w, K[(e + 3) * G3 + u], acc);
    }
    g_Xg[(dir * NB * T2 + bt) * G3 + u] = acc;
}

// ---------------------------------------------------------------------------
// Kernel B: GRU (reset_after=true, masked). grid (8,2), block 192.
// Thread u owns gate column u. R column kept in registers, h in smem.
// ---------------------------------------------------------------------------
__global__ void k_gru(const int* __restrict__ char_seq,
                      const float* __restrict__ Rf, const float* __restrict__ bf,
                      const float* __restrict__ Rb, const float* __restrict__ bb) {
    int b = blockIdx.x, dir = blockIdx.y;
    int u = threadIdx.x;
    const float* R    = dir ? Rb : Rf;
    const float* bias = dir ? bb : bf;
    float Rcol[EE];
#pragma unroll
    for (int e = 0; e < EE; e++) Rcol[e] = R[e * G3 + u];
    float b1u = bias[G3 + u];

    __shared__ float h_sm[EE];
    __shared__ float r_sm[EE];
    __shared__ float hh_sm[EE];
    if (u < EE) h_sm[u] = 0.0f;
    float h = 0.0f, y = 0.0f;
    const float* X = g_Xg + (dir * NB + b) * T2 * G3;
    const int*   cs = char_seq + b * T2;
    __syncthreads();

    for (int t = 0; t < T2; t++) {
        int tt = dir ? (T2 - 1 - t) : t;
        float x = X[tt * G3 + u];
        bool m  = (cs[tt] != 0);
        float rg = b1u;
        const float4* h4 = (const float4*)h_sm;
#pragma unroll
        for (int e4i = 0; e4i < EE / 4; e4i++) {
            float4 hv = h4[e4i];
            rg = fmaf(hv.x, Rcol[e4i * 4 + 0], rg);
            rg = fmaf(hv.y, Rcol[e4i * 4 + 1], rg);
            rg = fmaf(hv.z, Rcol[e4i * 4 + 2], rg);
            rg = fmaf(hv.w, Rcol[e4i * 4 + 3], rg);
        }
        float z = 0.0f;
        if (u < EE) {
            z = 1.0f / (1.0f + expf(-(x + rg)));
        } else if (u < 2 * EE) {
            r_sm[u - EE] = 1.0f / (1.0f + expf(-(x + rg)));
        }
        __syncthreads();
        if (u >= 2 * EE) {
            hh_sm[u - 2 * EE] = tanhf(x + r_sm[u - 2 * EE] * rg);
        }
        __syncthreads();
        if (u < EE) {
            float hn = z * h + (1.0f - z) * hh_sm[u];
            if (m) { h = hn; y = hn; }
            h_sm[u] = h;
            g_ctx[(b * T2 + tt) * CTXD + dir * EE + u] = y;
        }
        __syncthreads();
    }
}

// ---------------------------------------------------------------------------
// Kernel C1: P0/P1 = ctx @ conv1_w[k], and c_s = ctx . w_c
// grid 1024 (b*128+s), block 128
// ---------------------------------------------------------------------------
__global__ void k_p(const float* __restrict__ conv1_w,
                    const float* __restrict__ w_char) {
    int bs = blockIdx.x;
    int tid = threadIdx.x;
    __shared__ float c_sm[CTXD];
    __shared__ float red[CTXD];
    float cv = g_ctx[bs * CTXD + tid];
    c_sm[tid] = cv;
    red[tid]  = cv * w_char[DLN + tid];
    __syncthreads();
    for (int off = 64; off > 0; off >>= 1) {
        if (tid < off) red[tid] += red[tid + off];
        __syncthreads();
    }
    if (tid == 0) g_cs[bs] = red[0];

    int half = tid >> 6, o = tid & 63;
    const float* W = conv1_w + half * CTXD * EE;
    float acc = 0.0f;
    const float4* c4 = (const float4*)c_sm;
#pragma unroll
    for (int c4i = 0; c4i < CTXD / 4; c4i++) {
        float4 hv = c4[c4i];
        int c = c4i * 4;
        acc = fmaf(hv.x, W[(c + 0) * EE + o], acc);
        acc = fmaf(hv.y, W[(c + 1) * EE + o], acc);
        acc = fmaf(hv.z, W[(c + 2) * EE + o], acc);
        acc = fmaf(hv.w, W[(c + 3) * EE + o], acc);
    }
    if (half) g_P1[bs * EE + o] = acc; else g_P0[bs * EE + o] = acc;
}

// ---------------------------------------------------------------------------
// Kernel C2: Q00, Qm=Q10+Q01, Q11 from P @ conv2_w; bias2
// grid 1024, block 64
// ---------------------------------------------------------------------------
__global__ void k_q(const float* __restrict__ conv2_w,
                    const float* __restrict__ conv1_b,
                    const float* __restrict__ conv2_b) {
    int bs = blockIdx.x, o = threadIdx.x;
    __shared__ float p0[EE], p1[EE];
    p0[o] = g_P0[bs * EE + o];
    p1[o] = g_P1[bs * EE + o];
    __syncthreads();
    const float* W0 = conv2_w;
    const float* W1 = conv2_w + EE * EE;
    float q00 = 0.f, q10 = 0.f, q01 = 0.f, q11 = 0.f;
#pragma unroll
    for (int i = 0; i < EE; i++) {
        float w0 = W0[i * EE + o], w1 = W1[i * EE + o];
        float a = p0[i], c = p1[i];
        q00 = fmaf(a, w0, q00);
        q10 = fmaf(c, w0, q10);
        q01 = fmaf(a, w1, q01);
        q11 = fmaf(c, w1, q11);
    }
    g_Q00[bs * EE + o] = q00;
    g_Qm [bs * EE + o] = q10 + q01;
    g_Q11[bs * EE + o] = q11;
    if (bs == 0) {
        float bb = conv2_b[o];
#pragma unroll
        for (int i = 0; i < EE; i++) bb = fmaf(conv1_b[i], W0[i * EE + o] + W1[i * EE + o], bb);
        g_bias2[o] = bb;
    }
}

// ---------------------------------------------------------------------------
// Kernel C3: a[b,t] = lstm_outs[b,t] . w_l   (one warp per (b,t))
// grid 512, block 256 (8 warps)
// ---------------------------------------------------------------------------
__global__ void k_a(const float* __restrict__ lstm,
                    const float* __restrict__ w_char) {
    int warp = threadIdx.x >> 5, lane = threadIdx.x & 31;
    int bt = blockIdx.x * 8 + warp;
    const float* row = lstm + (long)bt * DLN;
    float acc = 0.0f;
#pragma unroll
    for (int k = 0; k < DLN / 32; k++)
        acc = fmaf(row[lane + 32 * k], w_char[lane + 32 * k], acc);
#pragma unroll
    for (int off = 16; off; off >>= 1)
        acc += __shfl_xor_sync(0xffffffffu, acc, off);
    if (lane == 0) g_a[bt] = acc;
}

// ---------------------------------------------------------------------------
// Kernel D: score + char_weights + max_s(c2) via Q decomposition
// grid (8, 32), block 1024 (16 t-rows x 64 o)
// ---------------------------------------------------------------------------
__global__ void __launch_bounds__(1024) k_main(const float* __restrict__ w_char,
                                               const float* __restrict__ b_char,
                                               float* __restrict__ out_final,
                                               float* __restrict__ out_cw) {
    int b = blockIdx.x, t0 = blockIdx.y * 16;
    int tl = threadIdx.x >> 6, o = threadIdx.x & 63;
    int t = t0 + tl;
    __shared__ float g[T2];
    __shared__ float A_sm[16];
    __shared__ float b2[EE];
    float w_t = w_char[DLN + CTXD];
    float w_i = w_char[DLN + CTXD + 1];
    float bc  = b_char[0];
    if (threadIdx.x < T2) g[threadIdx.x] = g_cs[b * T2 + threadIdx.x] + w_i * (float)threadIdx.x;
    if (threadIdx.x < 16) A_sm[threadIdx.x] = g_a[b * T1 + t0 + threadIdx.x] + w_t * (float)(t0 + threadIdx.x) + bc;
    if (threadIdx.x < EE) b2[threadIdx.x] = g_bias2[threadIdx.x];
    __syncthreads();
    float A = A_sm[tl];

    // char_weights = score (shape (b,t,128,1))
    float* cw = out_cw + ((long)(b * T1 + t)) * T2;
    cw[o]      = A + g[o];
    cw[64 + o] = A + g[64 + o];

    const float* Q00 = g_Q00 + b * T2 * EE + o;
    const float* Qm  = g_Qm  + b * T2 * EE + EE + o;        // indexed at s+1
    const float* Q11 = g_Q11 + b * T2 * EE + 2 * EE + o;    // indexed at s+2
    float bias = b2[o];
    float mx = -INFINITY;
#pragma unroll 3
    for (int s = 0; s < T2 - 2; s++) {
        float v = bias;
        v = fmaf(A + g[s],     Q00[s * EE], v);
        v = fmaf(A + g[s + 1], Qm [s * EE], v);
        v = fmaf(A + g[s + 2], Q11[s * EE], v);
        mx = fmaxf(mx, v);
    }
    out_final[((long)(b * T1 + t)) * EE + o] = mx;
}

// ---------------------------------------------------------------------------
extern "C" void kernel_launch(void* const* d_in, const int* in_sizes, int n_in,
                              void* d_out, int out_size) {
    const float* lstm     = (const float*)d_in[0];
    const int*   char_seq = (const int*)  d_in[1];
    const float* emb      = (const float*)d_in[2];
    const float* Kf       = (const float*)d_in[3];
    const float* Rf       = (const float*)d_in[4];
    const float* bf       = (const float*)d_in[5];
    const float* Kb       = (const float*)d_in[6];
    const float* Rb       = (const float*)d_in[7];
    const float* bb       = (const float*)d_in[8];
    const float* w_char   = (const float*)d_in[9];
    const float* b_char   = (const float*)d_in[10];
    const float* conv1_w  = (const float*)d_in[11];
    const float* conv1_b  = (const float*)d_in[12];
    const float* conv2_w  = (const float*)d_in[13];
    const float* conv2_b  = (const float*)d_in[14];

    float* out_final = (float*)d_out;                       // (8,512,64)
    float* out_cw    = out_final + NB * T1 * EE;            // (8,512,128,1)

    k_embed_xg<<<NB * T2, 2 * G3>>>(char_seq, emb, Kf, bf, Kb, bb);
    k_a<<<NB * T1 / 8, 256>>>(lstm, w_char);
    k_gru<<<dim3(NB, 2), G3>>>(char_seq, Rf, bf, Rb, bb);
    k_p<<<NB * T2, CTXD>>>(conv1_w, w_char);
    k_q<<<NB * T2, EE>>>(conv2_w, conv1_b, conv2_b);
    k_main<<<dim3(NB, T1 / 16), 1024>>>(w_char, b_char, out_final, out_cw);
}

// round 4
// speedup vs baseline: 1.1997x; 1.1997x over previous
#include <cuda_runtime.h>
#include <math.h>

// Problem constants
#define NB   8
#define T1   512
#define T2   128
#define EE   64      // E
#define G3   192     // 3*E
#define DLN  256
#define CTXD 128     // 2*E
#define VOC  129     // LA+1

// Scratch (device globals)
__device__ float g_tab[2 * VOC * G3];        // per-dir input-gate table
__device__ float g_ctx[NB * T2 * CTXD];      // [b][s][fwd|bwd]
__device__ float g_Q00[NB * T2 * EE];
__device__ float g_Qm [NB * T2 * EE];
__device__ float g_Q11[NB * T2 * EE];
__device__ float g_S1 [NB * T2 * EE];
__device__ float g_S2 [NB * T2 * EE];
__device__ float g_cs[NB * T2];              // ctx . w_c
__device__ float g_bias2[EE];

__device__ __forceinline__ float fsigmoid(float v) {
    return __fdividef(1.0f, 1.0f + __expf(-v));
}
__device__ __forceinline__ float ftanh(float v) {
    return fmaf(2.0f, __fdividef(1.0f, 1.0f + __expf(-2.0f * v)), -1.0f);
}

// ---------------------------------------------------------------------------
// Kernel T: input-gate table  tab[dir][c][u] = emb[c]@K_dir + b0[u]
// grid (129,2), block 192
// ---------------------------------------------------------------------------
__global__ void k_tab(const float* __restrict__ emb_table,
                      const float* __restrict__ Kf, const float* __restrict__ bf,
                      const float* __restrict__ Kb, const float* __restrict__ bb) {
    int c = blockIdx.x, dir = blockIdx.y;
    int u = threadIdx.x;
    __shared__ float e_sm[EE];
    if (u < EE) e_sm[u] = emb_table[c * EE + u];
    __syncthreads();
    const float* K = dir ? Kb : Kf;
    float a0 = (dir ? bb : bf)[u], a1 = 0.f, a2 = 0.f, a3 = 0.f;
    const float4* e4 = (const float4*)e_sm;
#pragma unroll
    for (int k = 0; k < 16; k++) {
        float4 hv = e4[k];
        int e = 4 * k;
        a0 = fmaf(hv.x, K[(e + 0) * G3 + u], a0);
        a1 = fmaf(hv.y, K[(e + 1) * G3 + u], a1);
        a2 = fmaf(hv.z, K[(e + 2) * G3 + u], a2);
        a3 = fmaf(hv.w, K[(e + 3) * G3 + u], a3);
    }
    g_tab[(dir * VOC + c) * G3 + u] = (a0 + a1) + (a2 + a3);
}

// ---------------------------------------------------------------------------
// Kernel G: GRU. grid (8,2), block 384 (= 192 cols x 2 e-halves).
// All x pre-staged in smem; 2 barriers/step; 4-acc matvec + 1 shfl.
// ---------------------------------------------------------------------------
__global__ void __launch_bounds__(384) k_gru(const int* __restrict__ char_seq,
                      const float* __restrict__ Rf, const float* __restrict__ bf,
                      const float* __restrict__ Rb, const float* __restrict__ bb) {
    extern __shared__ float x_sm[];              // [128][192]
    __shared__ float h_sm[EE];
    __shared__ float z_sm[EE];
    __shared__ float r_sm[EE];
    __shared__ int   s_char[T2];
    int b = blockIdx.x, dir = blockIdx.y;
    int tid = threadIdx.x;
    int col = tid >> 1, half = tid & 1;
    int gate = col >> 6, i = col & 63;

    const float* R    = dir ? Rb : Rf;
    const float* bias = dir ? bb : bf;
    float Rc[32];
#pragma unroll
    for (int e = 0; e < 32; e++) Rc[e] = R[(half * 32 + e) * G3 + col];
    float bcol = (half == 0) ? bias[G3 + col] : 0.0f;

    if (tid < T2) s_char[tid] = char_seq[b * T2 + tid];
    if (tid < EE) h_sm[tid] = 0.0f;
    __syncthreads();

    const float* tab = g_tab + dir * VOC * G3;
    for (int idx = tid; idx < T2 * G3; idx += 384) {
        int row = idx / G3, cc = idx - row * G3;
        x_sm[idx] = tab[s_char[row] * G3 + cc];
    }
    __syncthreads();

    float h = 0.0f, y = 0.0f;
    for (int t = 0; t < T2; t++) {
        int tt = dir ? (T2 - 1 - t) : t;
        float x = x_sm[tt * G3 + col];
        const float4* h4 = (const float4*)h_sm + half * 8;
        float a0 = bcol, a1 = 0.f, a2 = 0.f, a3 = 0.f;
#pragma unroll
        for (int k = 0; k < 8; k++) {
            float4 hv = h4[k];
            a0 = fmaf(hv.x, Rc[4 * k + 0], a0);
            a1 = fmaf(hv.y, Rc[4 * k + 1], a1);
            a2 = fmaf(hv.z, Rc[4 * k + 2], a2);
            a3 = fmaf(hv.w, Rc[4 * k + 3], a3);
        }
        float sum = (a0 + a1) + (a2 + a3);
        sum += __shfl_xor_sync(0xffffffffu, sum, 1);    // full rg(col)
        if (half == 0) {
            if (gate == 0)      z_sm[i] = fsigmoid(x + sum);
            else if (gate == 1) r_sm[i] = fsigmoid(x + sum);
        }
        __syncthreads();
        if (half == 0 && gate == 2) {
            float hh = ftanh(fmaf(r_sm[i], sum, x));
            float z  = z_sm[i];
            float hn = fmaf(z, h - hh, hh);              // z*h + (1-z)*hh
            if (s_char[tt] != 0) { h = hn; y = hn; }
            h_sm[i] = h;
            g_ctx[(b * T2 + tt) * CTXD + dir * EE + i] = y;
        }
        __syncthreads();
    }
}

// ---------------------------------------------------------------------------
// Kernel PQ: per (b,s): cs = ctx.w_c ; P0/P1 = ctx@W1 ; Q00/Qm/Q11 = P@W2
// grid 1024, block 128
// ---------------------------------------------------------------------------
__global__ void k_pq(const float* __restrict__ conv1_w,
                     const float* __restrict__ conv2_w,
                     const float* __restrict__ conv1_b,
                     const float* __restrict__ conv2_b,
                     const float* __restrict__ w_char) {
    int bs = blockIdx.x;
    int tid = threadIdx.x;
    __shared__ float c_sm[CTXD];
    __shared__ float wsum[4];
    __shared__ float p_sm[2][EE];
    __shared__ float q01_sm[EE];

    float cv = g_ctx[bs * CTXD + tid];
    c_sm[tid] = cv;
    float pv = cv * w_char[DLN + tid];
#pragma unroll
    for (int off = 16; off; off >>= 1) pv += __shfl_xor_sync(0xffffffffu, pv, off);
    if ((tid & 31) == 0) wsum[tid >> 5] = pv;
    __syncthreads();
    if (tid == 0) g_cs[bs] = (wsum[0] + wsum[1]) + (wsum[2] + wsum[3]);

    int half = tid >> 6, o = tid & 63;
    const float* W = conv1_w + half * CTXD * EE;
    float a0 = 0.f, a1 = 0.f, a2 = 0.f, a3 = 0.f;
    const float4* c4 = (const float4*)c_sm;
#pragma unroll
    for (int k = 0; k < CTXD / 4; k++) {
        float4 hv = c4[k];
        int c = 4 * k;
        a0 = fmaf(hv.x, W[(c + 0) * EE + o], a0);
        a1 = fmaf(hv.y, W[(c + 1) * EE + o], a1);
        a2 = fmaf(hv.z, W[(c + 2) * EE + o], a2);
        a3 = fmaf(hv.w, W[(c + 3) * EE + o], a3);
    }
    p_sm[half][o] = (a0 + a1) + (a2 + a3);
    __syncthreads();

    const float* W20 = conv2_w;
    const float* W21 = conv2_w + EE * EE;
    const float* P = p_sm[half];
    float qa0 = 0.f, qa1 = 0.f, qb0 = 0.f, qb1 = 0.f;   // (W20, W21) x 2 sub-accs
#pragma unroll
    for (int k = 0; k < EE; k += 2) {
        float pA = P[k], pB = P[k + 1];
        qa0 = fmaf(pA, W20[k * EE + o], qa0);
        qb0 = fmaf(pA, W21[k * EE + o], qb0);
        qa1 = fmaf(pB, W20[(k + 1) * EE + o], qa1);
        qb1 = fmaf(pB, W21[(k + 1) * EE + o], qb1);
    }
    float qW20 = qa0 + qa1;   // P@W20
    float qW21 = qb0 + qb1;   // P@W21
    if (half == 0) {
        g_Q00[bs * EE + o] = qW20;
        q01_sm[o] = qW21;
    }
    __syncthreads();
    if (half == 1) {
        g_Qm [bs * EE + o] = qW20 + q01_sm[o];   // P1@W20 + P0@W21
        g_Q11[bs * EE + o] = qW21;
    }
    if (bs == 0 && half == 0) {
        float bb2 = conv2_b[o];
#pragma unroll
        for (int k = 0; k < EE; k++)
            bb2 = fmaf(conv1_b[k], W20[k * EE + o] + W21[k * EE + o], bb2);
        g_bias2[o] = bb2;
    }
}

// ---------------------------------------------------------------------------
// Kernel S: S1[s]=Q00[s]+Qm[s+1]+Q11[s+2]; S2[s]=g(s)Q00+g(s+1)Qm+g(s+2)Q11+b2
// grid (8,128), block 64.  s>=126 -> S1=0, S2=-inf (padding for clean unroll)
// ---------------------------------------------------------------------------
__global__ void k_s(const float* __restrict__ w_char) {
    int b = blockIdx.x, s = blockIdx.y, o = threadIdx.x;
    int base = b * T2 * EE;
    int idx = base + s * EE + o;
    if (s < T2 - 2) {
        float wi = w_char[DLN + CTXD + 1];
        float g0 = g_cs[b * T2 + s]     + wi * (float)s;
        float g1 = g_cs[b * T2 + s + 1] + wi * (float)(s + 1);
        float g2 = g_cs[b * T2 + s + 2] + wi * (float)(s + 2);
        float q0 = g_Q00[idx];
        float qm = g_Qm [base + (s + 1) * EE + o];
        float q1 = g_Q11[base + (s + 2) * EE + o];
        g_S1[idx] = (q0 + qm) + q1;
        g_S2[idx] = fmaf(g0, q0, fmaf(g1, qm, fmaf(g2, q1, g_bias2[o])));
    } else {
        g_S1[idx] = 0.0f;
        g_S2[idx] = -INFINITY;
    }
}

// ---------------------------------------------------------------------------
// Kernel D: A = lstm.w_l + w_t*t + bc (inline); cw = A + g[s];
//           final = max_s(A*S1[s] + S2[s])
// grid (8,32), block 1024 (16 t x 64 o)
// ---------------------------------------------------------------------------
__global__ void __launch_bounds__(1024) k_main(const float* __restrict__ lstm,
                                               const float* __restrict__ w_char,
                                               const float* __restrict__ b_char,
                                               float* __restrict__ out_final,
                                               float* __restrict__ out_cw) {
    int b = blockIdx.x, t0 = blockIdx.y * 16;
    int tid = threadIdx.x;
    int tl = tid >> 6, o = tid & 63;
    int t = t0 + tl;
    __shared__ float asum[32];
    __shared__ float garr[T2];

    // inline a[b,t] = lstm[b,t] . w_l  (64 threads per t, float4 each)
    const float4* row4 = (const float4*)(lstm + ((long)(b * T1 + t)) * DLN);
    const float4* wl4  = (const float4*)w_char;
    float4 rv = row4[o], wv = wl4[o];
    float pv = rv.x * wv.x + rv.y * wv.y + rv.z * wv.z + rv.w * wv.w;
#pragma unroll
    for (int off = 16; off; off >>= 1) pv += __shfl_xor_sync(0xffffffffu, pv, off);
    if ((tid & 31) == 0) asum[tid >> 5] = pv;

    float wi = w_char[DLN + CTXD + 1];
    if (tid < T2) garr[tid] = g_cs[b * T2 + tid] + wi * (float)tid;
    __syncthreads();

    float wt = w_char[DLN + CTXD];
    float A = (asum[2 * tl] + asum[2 * tl + 1]) + wt * (float)t + b_char[0];

    // char_weights = score
    float* cw = out_cw + ((long)(b * T1 + t)) * T2;
    cw[o]      = A + garr[o];
    cw[64 + o] = A + garr[64 + o];

    const float* S1 = g_S1 + b * T2 * EE + o;
    const float* S2 = g_S2 + b * T2 * EE + o;
    float m0 = -INFINITY, m1 = -INFINITY, m2 = -INFINITY, m3 = -INFINITY;
#pragma unroll 4
    for (int s = 0; s < T2; s += 4) {
        float v0 = fmaf(A, S1[(s + 0) * EE], S2[(s + 0) * EE]);
        float v1 = fmaf(A, S1[(s + 1) * EE], S2[(s + 1) * EE]);
        float v2 = fmaf(A, S1[(s + 2) * EE], S2[(s + 2) * EE]);
        float v3 = fmaf(A, S1[(s + 3) * EE], S2[(s + 3) * EE]);
        m0 = fmaxf(m0, v0); m1 = fmaxf(m1, v1);
        m2 = fmaxf(m2, v2); m3 = fmaxf(m3, v3);
    }
    out_final[((long)(b * T1 + t)) * EE + o] = fmaxf(fmaxf(m0, m1), fmaxf(m2, m3));
}

// ---------------------------------------------------------------------------
extern "C" void kernel_launch(void* const* d_in, const int* in_sizes, int n_in,
                              void* d_out, int out_size) {
    const float* lstm     = (const float*)d_in[0];
    const int*   char_seq = (const int*)  d_in[1];
    const float* emb      = (const float*)d_in[2];
    const float* Kf       = (const float*)d_in[3];
    const float* Rf       = (const float*)d_in[4];
    const float* bf       = (const float*)d_in[5];
    const float* Kb       = (const float*)d_in[6];
    const float* Rb       = (const float*)d_in[7];
    const float* bb       = (const float*)d_in[8];
    const float* w_char   = (const float*)d_in[9];
    const float* b_char   = (const float*)d_in[10];
    const float* conv1_w  = (const float*)d_in[11];
    const float* conv1_b  = (const float*)d_in[12];
    const float* conv2_w  = (const float*)d_in[13];
    const float* conv2_b  = (const float*)d_in[14];

    float* out_final = (float*)d_out;                 // (8,512,64)
    float* out_cw    = out_final + NB * T1 * EE;      // (8,512,128,1)

    // Unconditional (no static guard — harness rule). Host-side, idempotent,
    // not stream-ordered, so safe under graph capture.
    cudaFuncSetAttribute(k_gru, cudaFuncAttributeMaxDynamicSharedMemorySize,
                         T2 * G3 * (int)sizeof(float));

    k_tab<<<dim3(VOC, 2), G3>>>(emb, Kf, bf, Kb, bb);
    k_gru<<<dim3(NB, 2), 384, T2 * G3 * sizeof(float)>>>(char_seq, Rf, bf, Rb, bb);
    k_pq<<<NB * T2, CTXD>>>(conv1_w, conv2_w, conv1_b, conv2_b, w_char);
    k_s<<<dim3(NB, T2), EE>>>(w_char);
    k_main<<<dim3(NB, T1 / 16), 1024>>>(lstm, w_char, b_char, out_final, out_cw);
}